// round 1
// baseline (speedup 1.0000x reference)
#include <cuda_runtime.h>
#include <cuda_bf16.h>
#include <math.h>

// Problem constants
#define B_   4096
#define D_   784
#define HALF_ 392
#define HID_ 512
#define CONDN_ 10
#define NBLK_ 20

// GEMM tile config
#define BM 128
#define BN 64
#define BK 8
#define TM 8
#define TN 4
// 256 threads per CTA

// ---------------- device scratch (no allocation allowed) ----------------
__device__ float g_v [B_ * D_];     // carry v between blocks
__device__ float g_xa[B_ * HALF_];  // x1 (permuted first half)
__device__ float g_xb[B_ * HALF_];  // x2 (permuted second half)
__device__ float g_h [B_ * HID_];   // hidden activations
__device__ float g_r [B_ * D_];     // subnet output r = [s | t]

// ---------------- kernels ----------------

__global__ void zero_kernel(float* __restrict__ p, int n) {
    int i = blockIdx.x * blockDim.x + threadIdx.x;
    if (i < n) p[i] = 0.f;
}

// x_perm[i, j] = v[i, perm[j]];  split into xa (j<392) and xb (j>=392)
__global__ void permute_kernel(const float* __restrict__ v,
                               const int* __restrict__ perm,
                               float* __restrict__ xa,
                               float* __restrict__ xb) {
    int idx = blockIdx.x * blockDim.x + threadIdx.x;
    if (idx >= B_ * D_) return;
    int i = idx / D_;
    int j = idx - i * D_;
    float val = v[(size_t)i * D_ + perm[j]];
    if (j < HALF_) xa[(size_t)i * HALF_ + j] = val;
    else           xb[(size_t)i * HALF_ + (j - HALF_)] = val;
}

// C[m,n] = act( A[m,:] @ W[:K,:] + bias[n] (+ W[K + lab[m], n]) )
// A: [4096, K] with row stride lda. W: [KW, N] row-major. C row stride ldc.
template<bool RELU, bool COND>
__global__ __launch_bounds__(256)
void gemm_kernel(const float* __restrict__ A, int lda,
                 const float* __restrict__ W,
                 const float* __restrict__ bias,
                 const int* __restrict__ lab,
                 float* __restrict__ C, int ldc,
                 int K, int N) {
    __shared__ float As[BK][BM];
    __shared__ float Bs[BK][BN + 4];

    const int tid = threadIdx.x;
    const int m0 = blockIdx.y * BM;
    const int n0 = blockIdx.x * BN;
    const int ty = tid >> 4;        // 0..15 -> m micro-tile
    const int tx = tid & 15;        // 0..15 -> n micro-tile

    // A tile load map: 128 rows x 8 k, float4 per thread
    const int ar = tid >> 1;        // 0..127
    const int ak = (tid & 1) * 4;   // 0 or 4
    // B tile load map: 8 rows x 64 n, 2 floats per thread
    const int bk = tid >> 5;        // 0..7
    const int bn = (tid & 31) * 2;  // 0..62

    float acc[TM][TN];
#pragma unroll
    for (int i = 0; i < TM; i++)
#pragma unroll
        for (int j = 0; j < TN; j++) acc[i][j] = 0.f;

    for (int k0 = 0; k0 < K; k0 += BK) {
        // load A tile (transposed into As[k][m])
        float4 av = *reinterpret_cast<const float4*>(
            A + (size_t)(m0 + ar) * lda + k0 + ak);
        As[ak + 0][ar] = av.x;
        As[ak + 1][ar] = av.y;
        As[ak + 2][ar] = av.z;
        As[ak + 3][ar] = av.w;
        // load B tile
        {
            int gn = n0 + bn;
            const float* wrow = W + (size_t)(k0 + bk) * N;
            Bs[bk][bn]     = (gn     < N) ? wrow[gn]     : 0.f;
            Bs[bk][bn + 1] = (gn + 1 < N) ? wrow[gn + 1] : 0.f;
        }
        __syncthreads();

#pragma unroll
        for (int kk = 0; kk < BK; kk++) {
            float a[TM], b[TN];
#pragma unroll
            for (int i = 0; i < TM; i++) a[i] = As[kk][ty * TM + i];
#pragma unroll
            for (int j = 0; j < TN; j++) b[j] = Bs[kk][tx * TN + j];
#pragma unroll
            for (int i = 0; i < TM; i++)
#pragma unroll
                for (int j = 0; j < TN; j++)
                    acc[i][j] = fmaf(a[i], b[j], acc[i][j]);
        }
        __syncthreads();
    }

    // epilogue
#pragma unroll
    for (int i = 0; i < TM; i++) {
        int m = m0 + ty * TM + i;
        const float* wcond = nullptr;
        if (COND) wcond = W + (size_t)(K + lab[m]) * N;
#pragma unroll
        for (int j = 0; j < TN; j++) {
            int n = n0 + tx * TN + j;
            if (n < N) {
                float val = acc[i][j] + bias[n];
                if (COND) val += wcond[n];
                if (RELU) val = fmaxf(val, 0.f);
                C[(size_t)m * ldc + n] = val;
            }
        }
    }
}

// Coupling epilogue: given r = [s | t] (4096x784), other-half xo (4096x392):
//   ls = 0.636*atan(s);  y = exp(ls)*xo + t;  jac[i] += sum_j ls
// y written with row stride 784 (into the v buffer / output z buffer).
__global__ void epilogue_kernel(const float* __restrict__ r,
                                const float* __restrict__ xo,
                                float* __restrict__ y,
                                float* __restrict__ jac) {
    int i = blockIdx.x;
    int t = threadIdx.x;  // 128 threads
    const float* rrow = r + (size_t)i * D_;
    const float* xrow = xo + (size_t)i * HALF_;
    float* yrow = y + (size_t)i * D_;
    float lsum = 0.f;
    for (int j = t; j < HALF_; j += 128) {
        float s = rrow[j];
        float ls = 0.636f * atanf(s);
        lsum += ls;
        yrow[j] = expf(ls) * xrow[j] + rrow[HALF_ + j];
    }
    // reduce lsum across block
#pragma unroll
    for (int off = 16; off; off >>= 1)
        lsum += __shfl_down_sync(0xffffffffu, lsum, off);
    __shared__ float ws[4];
    if ((t & 31) == 0) ws[t >> 5] = lsum;
    __syncthreads();
    if (t == 0) jac[i] += ws[0] + ws[1] + ws[2] + ws[3];
}

// ---------------- host launcher ----------------

extern "C" void kernel_launch(void* const* d_in, const int* in_sizes, int n_in,
                              void* d_out, int out_size) {
    const float* x     = (const float*)d_in[0];
    const int*   l     = (const int*)  d_in[1];
    const int*   perms = (const int*)  d_in[2];
    const float* s1_W1 = (const float*)d_in[3];
    const float* s1_b1 = (const float*)d_in[4];
    const float* s1_W2 = (const float*)d_in[5];
    const float* s1_b2 = (const float*)d_in[6];
    const float* s2_W1 = (const float*)d_in[7];
    const float* s2_b1 = (const float*)d_in[8];
    const float* s2_W2 = (const float*)d_in[9];
    const float* s2_b2 = (const float*)d_in[10];

    float* z   = (float*)d_out;            // [4096, 784]
    float* jac = z + (size_t)B_ * D_;      // [4096]

    float *pv, *pxa, *pxb, *ph, *pr;
    cudaGetSymbolAddress((void**)&pv,  g_v);
    cudaGetSymbolAddress((void**)&pxa, g_xa);
    cudaGetSymbolAddress((void**)&pxb, g_xb);
    cudaGetSymbolAddress((void**)&ph,  g_h);
    cudaGetSymbolAddress((void**)&pr,  g_r);

    zero_kernel<<<(B_ + 255) / 256, 256>>>(jac, B_);

    const int permGrid = (B_ * D_ + 255) / 256;
    const dim3 gemm1Grid(HID_ / BN, B_ / BM);              // (8, 32)
    const dim3 gemm2Grid((D_ + BN - 1) / BN, B_ / BM);     // (13, 32)

    const size_t W1sz = (size_t)(HALF_ + CONDN_) * HID_;   // 402*512
    const size_t W2sz = (size_t)HID_ * D_;                 // 512*784

    for (int k = 0; k < NBLK_; k++) {
        const float* vsrc = (k == 0) ? x : pv;
        float* vdst = (k == NBLK_ - 1) ? z : pv;

        permute_kernel<<<permGrid, 256>>>(vsrc, perms + (size_t)k * D_, pxa, pxb);

        // ---- subnet s2: input x2 (pxb), produces y1 into vdst[:, :392] ----
        gemm_kernel<true, true><<<gemm1Grid, 256>>>(
            pxb, HALF_, s2_W1 + k * W1sz, s2_b1 + (size_t)k * HID_, l,
            ph, HID_, HALF_, HID_);
        gemm_kernel<false, false><<<gemm2Grid, 256>>>(
            ph, HID_, s2_W2 + k * W2sz, s2_b2 + (size_t)k * D_, nullptr,
            pr, D_, HID_, D_);
        epilogue_kernel<<<B_, 128>>>(pr, pxa, vdst, jac);  // y1 = exp(ls2)*x1 + t2

        // ---- subnet s1: input y1 (vdst, lda=784), produces y2 into vdst[:, 392:] ----
        gemm_kernel<true, true><<<gemm1Grid, 256>>>(
            vdst, D_, s1_W1 + k * W1sz, s1_b1 + (size_t)k * HID_, l,
            ph, HID_, HALF_, HID_);
        gemm_kernel<false, false><<<gemm2Grid, 256>>>(
            ph, HID_, s1_W2 + k * W2sz, s1_b2 + (size_t)k * D_, nullptr,
            pr, D_, HID_, D_);
        epilogue_kernel<<<B_, 128>>>(pr, pxb, vdst + HALF_, jac);  // y2 = exp(ls1)*x2 + t1
    }
}

// round 3
// speedup vs baseline: 2.1304x; 2.1304x over previous
#include <cuda_runtime.h>
#include <cuda_bf16.h>
#include <cstdint>
#include <math.h>

// Problem constants
#define B_     4096
#define D_     784
#define HALF_  392
#define HID_   512
#define CONDN_ 10
#define NBLK_  20

#define K1PAD  416          // 392 padded to 13*32
#define K2PAD  512
#define N2PAD  832          // 784 padded to 13*64

// GEMM tiling: CTA 128(M) x 64(N) x 32(K-stage), 8 warps of 32x32
#define TILE_M 128
#define TILE_N 64
#define TILE_K 32

// smem stage layout (bytes): rows padded 64B->80B for conflict-free ldmatrix
#define SA_ROW   80
#define ST_AHI   0
#define ST_ALO   10240
#define ST_BHI   20480
#define ST_BLO   25600
#define ST_SIZE  30720
#define SM_TOTAL (2 * ST_SIZE)

// ---------------- PTX helpers ----------------
__device__ __forceinline__ uint32_t smem_u32(const void* p) {
    uint32_t a;
    asm("{ .reg .u64 t; cvta.to.shared.u64 t, %1; cvt.u32.u64 %0, t; }" : "=r"(a) : "l"(p));
    return a;
}
#define CP_ASYNC16(dst, src) \
    asm volatile("cp.async.cg.shared.global [%0], [%1], 16;" :: "r"(dst), "l"(src))
#define CP_COMMIT() asm volatile("cp.async.commit_group;" ::: "memory")
#define CP_WAIT1()  asm volatile("cp.async.wait_group 1;" ::: "memory")
#define CP_WAIT0()  asm volatile("cp.async.wait_group 0;" ::: "memory")

__device__ __forceinline__ void ldm4(uint32_t& r0, uint32_t& r1, uint32_t& r2, uint32_t& r3,
                                     uint32_t a) {
    asm volatile("ldmatrix.sync.aligned.m8n8.x4.shared.b16 {%0,%1,%2,%3}, [%4];"
                 : "=r"(r0), "=r"(r1), "=r"(r2), "=r"(r3) : "r"(a));
}
__device__ __forceinline__ void mma_bf16(float& c0, float& c1, float& c2, float& c3,
                                         uint32_t a0, uint32_t a1, uint32_t a2, uint32_t a3,
                                         uint32_t b0, uint32_t b1) {
    asm volatile(
        "mma.sync.aligned.m16n8k16.row.col.f32.bf16.bf16.f32 "
        "{%0,%1,%2,%3}, {%4,%5,%6,%7}, {%8,%9}, {%0,%1,%2,%3};"
        : "+f"(c0), "+f"(c1), "+f"(c2), "+f"(c3)
        : "r"(a0), "r"(a1), "r"(a2), "r"(a3), "r"(b0), "r"(b1));
}

// ---------------- device scratch ----------------
__device__ float g_v [B_ * D_];
__device__ float g_xa[B_ * HALF_];
__device__ float g_xb[B_ * HALF_];
__device__ float g_r [B_ * D_];

__device__ __nv_bfloat16 g_xbs_hi[B_ * K1PAD];
__device__ __nv_bfloat16 g_xbs_lo[B_ * K1PAD];
__device__ __nv_bfloat16 g_ys_hi [B_ * K1PAD];
__device__ __nv_bfloat16 g_ys_lo [B_ * K1PAD];
__device__ __nv_bfloat16 g_h_hi  [B_ * K2PAD];
__device__ __nv_bfloat16 g_h_lo  [B_ * K2PAD];

// transposed + split weights: W1t [blk][512][416], W2t [blk][832][512]
__device__ __nv_bfloat16 g_s1w1_hi[NBLK_ * HID_ * K1PAD];
__device__ __nv_bfloat16 g_s1w1_lo[NBLK_ * HID_ * K1PAD];
__device__ __nv_bfloat16 g_s2w1_hi[NBLK_ * HID_ * K1PAD];
__device__ __nv_bfloat16 g_s2w1_lo[NBLK_ * HID_ * K1PAD];
__device__ __nv_bfloat16 g_s1w2_hi[NBLK_ * N2PAD * K2PAD];
__device__ __nv_bfloat16 g_s1w2_lo[NBLK_ * N2PAD * K2PAD];
__device__ __nv_bfloat16 g_s2w2_hi[NBLK_ * N2PAD * K2PAD];
__device__ __nv_bfloat16 g_s2w2_lo[NBLK_ * N2PAD * K2PAD];

// ---------------- small kernels ----------------
__global__ void zero_kernel(float* __restrict__ p, int n) {
    int i = blockIdx.x * blockDim.x + threadIdx.x;
    if (i < n) p[i] = 0.f;
}

__device__ __forceinline__ void split1(float v, __nv_bfloat16& h, __nv_bfloat16& l) {
    h = __float2bfloat16_rn(v);
    l = __float2bfloat16_rn(v - __bfloat162float(h));
}

// permute + split second half. idx covers B_ x 808 (784 data + 24 pad)
__global__ void permute_kernel(const float* __restrict__ v,
                               const int* __restrict__ perm,
                               float* __restrict__ xa,
                               float* __restrict__ xb,
                               __nv_bfloat16* __restrict__ xbh,
                               __nv_bfloat16* __restrict__ xbl) {
    int idx = blockIdx.x * blockDim.x + threadIdx.x;
    const int W = D_ + (K1PAD - HALF_);  // 808
    if (idx >= B_ * W) return;
    int i = idx / W;
    int j = idx - i * W;
    if (j < D_) {
        float val = v[(size_t)i * D_ + perm[j]];
        if (j < HALF_) {
            xa[(size_t)i * HALF_ + j] = val;
        } else {
            int jj = j - HALF_;
            xb[(size_t)i * HALF_ + jj] = val;
            __nv_bfloat16 h, l;
            split1(val, h, l);
            xbh[(size_t)i * K1PAD + jj] = h;
            xbl[(size_t)i * K1PAD + jj] = l;
        }
    } else {
        int jj = HALF_ + (j - D_);       // pad region 392..415
        xbh[(size_t)i * K1PAD + jj] = __float2bfloat16_rn(0.f);
        xbl[(size_t)i * K1PAD + jj] = __float2bfloat16_rn(0.f);
    }
}

// transpose + split weights: W[blk][Kfull][N] -> hi/lo[blk][Npad][Kpad]
__global__ void convert_w_kernel(const float* __restrict__ W,
                                 __nv_bfloat16* __restrict__ hi,
                                 __nv_bfloat16* __restrict__ lo,
                                 int Kfull, int Kuse, int Kpad, int Nvalid, int Npad) {
    __shared__ float t[16][17];
    int bk = blockIdx.x;
    int bn = blockIdx.y;
    int blk = blockIdx.z;
    int tx = threadIdx.x & 15, ty = threadIdx.x >> 4;
    int k = bk * 16 + ty, n = bn * 16 + tx;
    float v = (k < Kuse && n < Nvalid) ? W[((size_t)blk * Kfull + k) * Nvalid + n] : 0.f;
    t[ty][tx] = v;
    __syncthreads();
    float o = t[tx][ty];
    __nv_bfloat16 h, l;
    split1(o, h, l);
    size_t oidx = ((size_t)blk * Npad + bn * 16 + ty) * Kpad + bk * 16 + tx;
    hi[oidx] = h;
    lo[oidx] = l;
}

// coupling epilogue; optionally writes split-bf16 y for next GEMM
template<bool WSPLIT>
__global__ void epilogue_kernel(const float* __restrict__ r,
                                const float* __restrict__ xo,
                                float* __restrict__ y,
                                float* __restrict__ jac,
                                __nv_bfloat16* __restrict__ yh,
                                __nv_bfloat16* __restrict__ yl) {
    int i = blockIdx.x;
    int t = threadIdx.x;  // 128 threads
    const float* rrow = r + (size_t)i * D_;
    const float* xrow = xo + (size_t)i * HALF_;
    float* yrow = y + (size_t)i * D_;
    float lsum = 0.f;
    const int JEND = WSPLIT ? K1PAD : HALF_;
    for (int j = t; j < JEND; j += 128) {
        if (j < HALF_) {
            float s = rrow[j];
            float ls = 0.636f * atanf(s);
            lsum += ls;
            float yv = expf(ls) * xrow[j] + rrow[HALF_ + j];
            yrow[j] = yv;
            if (WSPLIT) {
                __nv_bfloat16 h, l;
                split1(yv, h, l);
                yh[(size_t)i * K1PAD + j] = h;
                yl[(size_t)i * K1PAD + j] = l;
            }
        } else if (WSPLIT) {
            yh[(size_t)i * K1PAD + j] = __float2bfloat16_rn(0.f);
            yl[(size_t)i * K1PAD + j] = __float2bfloat16_rn(0.f);
        }
    }
#pragma unroll
    for (int off = 16; off; off >>= 1)
        lsum += __shfl_down_sync(0xffffffffu, lsum, off);
    __shared__ float ws[4];
    if ((t & 31) == 0) ws[t >> 5] = lsum;
    __syncthreads();
    if (t == 0) jac[i] += ws[0] + ws[1] + ws[2] + ws[3];
}

// ---------------- HMMA GEMM ----------------
// C[m,n] = act( A[m,:] @ Bt[n,:]^T + bias[n] (+ Wcond[(392+lab[m])*ldcond + n]) )
// A: split bf16 [4096][Ka]; Bt: split bf16 [Npad][Ka]. 3-term split product.
// SPLIT_OUT: relu + write split bf16 (Chi/Clo, stride ldc). else fp32 (Cf, stride ldc, n<Nvalid).
template<bool SPLIT_OUT, bool COND>
__global__ __launch_bounds__(256)
void gemm_mma(const __nv_bfloat16* __restrict__ Ahi, const __nv_bfloat16* __restrict__ Alo,
              const __nv_bfloat16* __restrict__ Bhi, const __nv_bfloat16* __restrict__ Blo,
              int Ka, int nch,
              const float* __restrict__ bias,
              const float* __restrict__ Wcond, int ldcond, const int* __restrict__ lab,
              float* __restrict__ Cf,
              __nv_bfloat16* __restrict__ Chi, __nv_bfloat16* __restrict__ Clo,
              int ldc, int Nvalid) {
    extern __shared__ __align__(128) char sm[];
    const int tid = threadIdx.x;
    const int lane = tid & 31, wid = tid >> 5;
    const int wm = wid & 3, wn = wid >> 2;           // warp tile: 32(M) x 32(N)
    const int m0 = blockIdx.y * TILE_M, n0 = blockIdx.x * TILE_N;
    const uint32_t sb = smem_u32(sm);

    // cp.async maps
    const int a_row = tid >> 2, a_seg = tid & 3;     // A: rows 0..63 (+64), 4 segs of 16B
    const int b_row = tid >> 2, b_seg = tid & 3;     // B: rows 0..63

    float acc[2][4][4];
#pragma unroll
    for (int i = 0; i < 2; i++)
#pragma unroll
        for (int j = 0; j < 4; j++)
#pragma unroll
            for (int q = 0; q < 4; q++) acc[i][j][q] = 0.f;

#define LOAD_STAGE(c, s)                                                                  \
    do {                                                                                  \
        uint32_t st = sb + (s) * ST_SIZE;                                                 \
        const __nv_bfloat16* a0s = Ahi + (size_t)(m0 + a_row) * Ka + (c) * 32 + a_seg * 8;\
        const __nv_bfloat16* a1s = a0s + (size_t)64 * Ka;                                 \
        const __nv_bfloat16* a2s = Alo + (size_t)(m0 + a_row) * Ka + (c) * 32 + a_seg * 8;\
        const __nv_bfloat16* a3s = a2s + (size_t)64 * Ka;                                 \
        CP_ASYNC16(st + ST_AHI + a_row * SA_ROW + a_seg * 16, a0s);                       \
        CP_ASYNC16(st + ST_AHI + (a_row + 64) * SA_ROW + a_seg * 16, a1s);                \
        CP_ASYNC16(st + ST_ALO + a_row * SA_ROW + a_seg * 16, a2s);                       \
        CP_ASYNC16(st + ST_ALO + (a_row + 64) * SA_ROW + a_seg * 16, a3s);                \
        CP_ASYNC16(st + ST_BHI + b_row * SA_ROW + b_seg * 16,                             \
                   Bhi + (size_t)(n0 + b_row) * Ka + (c) * 32 + b_seg * 8);               \
        CP_ASYNC16(st + ST_BLO + b_row * SA_ROW + b_seg * 16,                             \
                   Blo + (size_t)(n0 + b_row) * Ka + (c) * 32 + b_seg * 8);               \
    } while (0)

    LOAD_STAGE(0, 0);
    CP_COMMIT();

    // ldmatrix lane address components
    const uint32_t a_lrow = (lane & 15);
    const uint32_t a_lcol = (lane >> 4) << 4;                       // 0 or 16 bytes
    const uint32_t b_lrow = (lane & 7) + ((lane & 16) >> 1);        // 0..15
    const uint32_t b_lcol = (lane & 8) << 1;                        // 0 or 16 bytes

    for (int c = 0; c < nch; c++) {
        if (c + 1 < nch) {
            LOAD_STAGE(c + 1, (c + 1) & 1);
            CP_COMMIT();
            CP_WAIT1();
        } else {
            CP_WAIT0();
        }
        __syncthreads();

        uint32_t st = sb + (c & 1) * ST_SIZE;
#pragma unroll
        for (int s = 0; s < 2; s++) {
            uint32_t a[2][2][4];   // [hl][mm][4]
            uint32_t b[2][4][2];   // [hl][n8][2]
#pragma unroll
            for (int hl = 0; hl < 2; hl++) {
#pragma unroll
                for (int mm = 0; mm < 2; mm++) {
                    uint32_t ad = st + (hl ? ST_ALO : ST_AHI)
                                + (wm * 32 + mm * 16 + a_lrow) * SA_ROW + a_lcol + s * 32;
                    ldm4(a[hl][mm][0], a[hl][mm][1], a[hl][mm][2], a[hl][mm][3], ad);
                }
#pragma unroll
                for (int nt = 0; nt < 2; nt++) {
                    uint32_t bd = st + (hl ? ST_BLO : ST_BHI)
                                + (wn * 32 + nt * 16 + b_lrow) * SA_ROW + b_lcol + s * 32;
                    ldm4(b[hl][2 * nt][0], b[hl][2 * nt][1],
                         b[hl][2 * nt + 1][0], b[hl][2 * nt + 1][1], bd);
                }
            }
#pragma unroll
            for (int mm = 0; mm < 2; mm++) {
#pragma unroll
                for (int nn = 0; nn < 4; nn++) {
                    float* cc = acc[mm][nn];
                    mma_bf16(cc[0], cc[1], cc[2], cc[3],
                             a[0][mm][0], a[0][mm][1], a[0][mm][2], a[0][mm][3],
                             b[0][nn][0], b[0][nn][1]);
                    mma_bf16(cc[0], cc[1], cc[2], cc[3],
                             a[0][mm][0], a[0][mm][1], a[0][mm][2], a[0][mm][3],
                             b[1][nn][0], b[1][nn][1]);
                    mma_bf16(cc[0], cc[1], cc[2], cc[3],
                             a[1][mm][0], a[1][mm][1], a[1][mm][2], a[1][mm][3],
                             b[0][nn][0], b[0][nn][1]);
                }
            }
        }
        __syncthreads();
    }
#undef LOAD_STAGE

    // ---- epilogue ----
    const int rbase = lane >> 2;
    const int cbase = (lane & 3) * 2;
#pragma unroll
    for (int mm = 0; mm < 2; mm++) {
#pragma unroll
        for (int h = 0; h < 2; h++) {
            int m = m0 + wm * 32 + mm * 16 + rbase + h * 8;
            const float* wc = nullptr;
            if (COND) wc = Wcond + (size_t)(HALF_ + lab[m]) * ldcond;
#pragma unroll
            for (int nn = 0; nn < 4; nn++) {
                int n = n0 + wn * 32 + nn * 8 + cbase;
                float v0 = acc[mm][nn][h * 2 + 0];
                float v1 = acc[mm][nn][h * 2 + 1];
                if (SPLIT_OUT) {
                    v0 += bias[n];     v1 += bias[n + 1];
                    if (COND) { v0 += wc[n]; v1 += wc[n + 1]; }
                    v0 = fmaxf(v0, 0.f);
                    v1 = fmaxf(v1, 0.f);
                    __nv_bfloat16 h0, l0, h1, l1;
                    split1(v0, h0, l0);
                    split1(v1, h1, l1);
                    __nv_bfloat162 hp; hp.x = h0; hp.y = h1;
                    __nv_bfloat162 lp; lp.x = l0; lp.y = l1;
                    *reinterpret_cast<__nv_bfloat162*>(Chi + (size_t)m * ldc + n) = hp;
                    *reinterpret_cast<__nv_bfloat162*>(Clo + (size_t)m * ldc + n) = lp;
                } else {
                    if (n < Nvalid) {
                        v0 += bias[n];     v1 += bias[n + 1];
                        if (COND) { v0 += wc[n]; v1 += wc[n + 1]; }
                        float2 o; o.x = v0; o.y = v1;
                        *reinterpret_cast<float2*>(Cf + (size_t)m * ldc + n) = o;
                    }
                }
            }
        }
    }
}

// ---------------- host launcher ----------------
extern "C" void kernel_launch(void* const* d_in, const int* in_sizes, int n_in,
                              void* d_out, int out_size) {
    const float* x     = (const float*)d_in[0];
    const int*   l     = (const int*)  d_in[1];
    const int*   perms = (const int*)  d_in[2];
    const float* s1_W1 = (const float*)d_in[3];
    const float* s1_b1 = (const float*)d_in[4];
    const float* s1_W2 = (const float*)d_in[5];
    const float* s1_b2 = (const float*)d_in[6];
    const float* s2_W1 = (const float*)d_in[7];
    const float* s2_b1 = (const float*)d_in[8];
    const float* s2_W2 = (const float*)d_in[9];
    const float* s2_b2 = (const float*)d_in[10];

    float* z   = (float*)d_out;
    float* jac = z + (size_t)B_ * D_;

    float *pv, *pxa, *pxb, *pr;
    cudaGetSymbolAddress((void**)&pv,  g_v);
    cudaGetSymbolAddress((void**)&pxa, g_xa);
    cudaGetSymbolAddress((void**)&pxb, g_xb);
    cudaGetSymbolAddress((void**)&pr,  g_r);

    __nv_bfloat16 *xbh, *xbl, *ysh, *ysl, *hh, *hl;
    cudaGetSymbolAddress((void**)&xbh, g_xbs_hi);
    cudaGetSymbolAddress((void**)&xbl, g_xbs_lo);
    cudaGetSymbolAddress((void**)&ysh, g_ys_hi);
    cudaGetSymbolAddress((void**)&ysl, g_ys_lo);
    cudaGetSymbolAddress((void**)&hh,  g_h_hi);
    cudaGetSymbolAddress((void**)&hl,  g_h_lo);

    __nv_bfloat16 *w1h[2], *w1l[2], *w2h[2], *w2l[2];
    cudaGetSymbolAddress((void**)&w1h[0], g_s1w1_hi);
    cudaGetSymbolAddress((void**)&w1l[0], g_s1w1_lo);
    cudaGetSymbolAddress((void**)&w1h[1], g_s2w1_hi);
    cudaGetSymbolAddress((void**)&w1l[1], g_s2w1_lo);
    cudaGetSymbolAddress((void**)&w2h[0], g_s1w2_hi);
    cudaGetSymbolAddress((void**)&w2l[0], g_s1w2_lo);
    cudaGetSymbolAddress((void**)&w2h[1], g_s2w2_hi);
    cudaGetSymbolAddress((void**)&w2l[1], g_s2w2_lo);

    cudaFuncSetAttribute(gemm_mma<true, true>,   cudaFuncAttributeMaxDynamicSharedMemorySize, SM_TOTAL);
    cudaFuncSetAttribute(gemm_mma<false, false>, cudaFuncAttributeMaxDynamicSharedMemorySize, SM_TOTAL);

    // weight conversion (every replay)
    {
        dim3 g1(K1PAD / 16, HID_ / 16, NBLK_);
        convert_w_kernel<<<g1, 256>>>(s1_W1, w1h[0], w1l[0], HALF_ + CONDN_, HALF_, K1PAD, HID_, HID_);
        convert_w_kernel<<<g1, 256>>>(s2_W1, w1h[1], w1l[1], HALF_ + CONDN_, HALF_, K1PAD, HID_, HID_);
        dim3 g2(K2PAD / 16, N2PAD / 16, NBLK_);
        convert_w_kernel<<<g2, 256>>>(s1_W2, w2h[0], w2l[0], HID_, HID_, K2PAD, D_, N2PAD);
        convert_w_kernel<<<g2, 256>>>(s2_W2, w2h[1], w2l[1], HID_, HID_, K2PAD, D_, N2PAD);
    }

    zero_kernel<<<(B_ + 255) / 256, 256>>>(jac, B_);

    const int PW = D_ + (K1PAD - HALF_);  // 808
    const int permGrid = (B_ * PW + 255) / 256;
    const dim3 g1Grid(HID_ / TILE_N,  B_ / TILE_M);   // (8, 32)
    const dim3 g2Grid(N2PAD / TILE_N, B_ / TILE_M);   // (13, 32)

    const size_t W1sz  = (size_t)(HALF_ + CONDN_) * HID_;
    const size_t W1tsz = (size_t)HID_ * K1PAD;
    const size_t W2tsz = (size_t)N2PAD * K2PAD;

    for (int k = 0; k < NBLK_; k++) {
        const float* vsrc = (k == 0) ? x : pv;
        float* vdst = (k == NBLK_ - 1) ? z : pv;

        permute_kernel<<<permGrid, 256>>>(vsrc, perms + (size_t)k * D_, pxa, pxb, xbh, xbl);

        // ---- subnet s2 on x2 -> y1 into vdst[:, :392] ----
        gemm_mma<true, true><<<g1Grid, 256, SM_TOTAL>>>(
            xbh, xbl, w1h[1] + k * W1tsz, w1l[1] + k * W1tsz,
            K1PAD, K1PAD / TILE_K,
            s2_b1 + (size_t)k * HID_, s2_W1 + k * W1sz, HID_, l,
            nullptr, hh, hl, HID_, HID_);
        gemm_mma<false, false><<<g2Grid, 256, SM_TOTAL>>>(
            hh, hl, w2h[1] + k * W2tsz, w2l[1] + k * W2tsz,
            K2PAD, K2PAD / TILE_K,
            s2_b2 + (size_t)k * D_, nullptr, 0, nullptr,
            pr, nullptr, nullptr, D_, D_);
        epilogue_kernel<true><<<B_, 128>>>(pr, pxa, vdst, jac, ysh, ysl);

        // ---- subnet s1 on y1 -> y2 into vdst[:, 392:] ----
        gemm_mma<true, true><<<g1Grid, 256, SM_TOTAL>>>(
            ysh, ysl, w1h[0] + k * W1tsz, w1l[0] + k * W1tsz,
            K1PAD, K1PAD / TILE_K,
            s1_b1 + (size_t)k * HID_, s1_W1 + k * W1sz, HID_, l,
            nullptr, hh, hl, HID_, HID_);
        gemm_mma<false, false><<<g2Grid, 256, SM_TOTAL>>>(
            hh, hl, w2h[0] + k * W2tsz, w2l[0] + k * W2tsz,
            K2PAD, K2PAD / TILE_K,
            s1_b2 + (size_t)k * D_, nullptr, 0, nullptr,
            pr, nullptr, nullptr, D_, D_);
        epilogue_kernel<false><<<B_, 128>>>(pr, pxb, vdst + HALF_, jac, nullptr, nullptr);
    }
}